// round 15
// baseline (speedup 1.0000x reference)
#include <cuda_runtime.h>
#include <math_constants.h>

#define IMG_H 64
#define IMG_W 2048
#define KNN_CUTOFF 1.0f

#define PTS_PER_WARP 3            // 10 lanes/point, lanes 30,31 idle
#define WARPS_PER_BLK 8
#define THREADS_FUSED (WARPS_PER_BLK * 32)          // 256
#define PTS_PER_BLK (WARPS_PER_BLK * PTS_PER_WARP)  // 24

// inv_g[k] = 1 - gauss(k)/sum(gauss), sigma=1, 5x5, row-major (ky,kx)
__device__ __constant__ float INV_G_C[25] = {
    0.99703098f, 0.98669378f, 0.97806177f, 0.98669378f, 0.99703098f,
    0.98669378f, 0.94036569f, 0.90167956f, 0.94036569f, 0.98669378f,
    0.97806177f, 0.90167956f, 0.83789717f, 0.90167956f, 0.97806177f,
    0.98669378f, 0.94036569f, 0.90167956f, 0.94036569f, 0.98669378f,
    0.99703098f, 0.98669378f, 0.97806177f, 0.98669378f, 0.99703098f
};

// ---------------------------------------------------------------------------
// COLD path (~65 of 131072 points): exact top-5 with reference tie-breaking.
// __noinline__ so its registers don't pollute the hot path.
// ---------------------------------------------------------------------------
__device__ __noinline__
unsigned knn_exact_top5(const float* __restrict__ proj_range,
                        int x0, int y0, float ur)
{
    unsigned key[25];
    unsigned ib = 0;
#pragma unroll
    for (int k = 0; k < 25; ++k) {
        const int yy = y0 + (k / 5) - 2;
        const int xx = x0 + (k % 5) - 2;
        const bool valid = ((unsigned)yy < (unsigned)IMG_H) &&
                           ((unsigned)xx < (unsigned)IMG_W);
        const int yyc = valid ? yy : 0;
        const int xxc = valid ? xx : 0;
        float rr = valid ? __ldg(proj_range + yyc * IMG_W + xxc) : 0.0f;
        if (rr < 0.0f) rr = CUDART_INF_F;   // matches reference
        if (k == 12)   rr = ur;             // center: d = 0
        key[k] = __float_as_uint(fabsf(rr - ur) * INV_G_C[k]);
        if (valid) ib |= (1u << k);
    }

    unsigned nm = 0;
#pragma unroll
    for (int sel = 0; sel < 5; ++sel) {
        unsigned long long best = ~0ull;
#pragma unroll
        for (int k = 0; k < 25; ++k) {
            const unsigned long long c =
                ((unsigned long long)key[k] << 32) | (unsigned)k;
            if (c < best) best = c;
        }
        const unsigned bi = (unsigned)(best & 0xFFFFFFFFu);
        nm |= (1u << bi);     // all 5 winners have d <= cutoff (>5 passers exist)
#pragma unroll
        for (int k = 0; k < 25; ++k)
            if ((unsigned)k == bi) key[k] = 0xFFFFFFFFu;
    }

    return nm & ib;           // OOB winners contribute zero probs: drop
}

// ---------------------------------------------------------------------------
// Fused kernel: 10 lanes/point (row x half), 3 points/warp, lanes 30,31 idle.
// One LDG.128 per lane covers the whole 5x5 window in a single instruction
// per warp (both quads of every row -> lines counted once). hi quad reaches
// the half-0 lane via shfl; masks combine via one REDUX. In-bounds mask is
// computed arithmetically (== pass AND valid). No smem, no __syncthreads.
// ---------------------------------------------------------------------------
__global__ __launch_bounds__(THREADS_FUSED, 7)
void knn_fused(const float*  __restrict__ proj_range,
               const float*  __restrict__ unproj,
               const float4* __restrict__ probs4,    // [H*W][5] float4
               const int*    __restrict__ px,
               const int*    __restrict__ py,
               float4*       __restrict__ out4,      // [P][5] float4
               int P)
{
    const int tid  = threadIdx.x;
    const int wrp  = tid >> 5;
    const int lane = tid & 31;
    const int g    = (lane * 103) >> 10;       // lane/10 (0..3; 3 = idle tail)
    const int q    = lane - g * 10;            // 0..9
    const int row  = (q >= 5) ? (q - 5) : q;   // window row / channel chunk
    const int half = (q >= 5) ? 1 : 0;         // which quad of the row
    const int p    = blockIdx.x * PTS_PER_BLK + wrp * PTS_PER_WARP + g;
    const bool pvalid = (g < 3) && (p < P);
    const int pc   = pvalid ? p : 0;           // clamped: safe loads, uniform flow

    // per-lane row weights (row fixed per lane -> no dynamic constant indexing)
    const int a = (row >= 2) ? (row - 2) : (2 - row);    // |row-2|
    const float wb0 = (a == 0) ? 0.83789717f : ((a == 1) ? 0.90167956f : 0.97806177f);
    const float wb1 = (a == 0) ? 0.90167956f : ((a == 1) ? 0.94036569f : 0.98669378f);
    const float wb2 = (a == 0) ? 0.97806177f : ((a == 1) ? 0.98669378f : 0.99703098f);

    const int   x0 = px[pc];
    const int   y0 = py[pc];
    const float ur = unproj[pc];

    const int  yy  = y0 + row - 2;
    const bool rv  = ((unsigned)yy < (unsigned)IMG_H);
    const int  yyc = rv ? yy : 0;
    const bool interior = (x0 >= 2) && (x0 <= IMG_W - 3);
    const int  xb   = x0 - 2;
    const int  base = xb & ~3;                 // aligned; W%4==0 so in-range
    const int  off  = xb & 3;

    // ------ ONE range load per lane: whole window in one warp instruction --
    float4 myq = make_float4(0.f, 0.f, 0.f, 0.f);
    if (interior)
        myq = __ldg((const float4*)(proj_range + yyc * IMG_W + base) + half);

    // hi quad of this row lives in lane+5; bring it to the half-0 lane
    float4 hq;
    hq.x = __shfl_down_sync(0xFFFFFFFFu, myq.x, 5);
    hq.y = __shfl_down_sync(0xFFFFFFFFu, myq.y, 5);
    hq.z = __shfl_down_sync(0xFFFFFFFFu, myq.z, 5);
    hq.w = __shfl_down_sync(0xFFFFFFFFu, myq.w, 5);

    // ------ half-0 lane builds this row's cutoff bits ---------------------
    unsigned partAll = 0;
    if (half == 0) {
        const float w[5] = { wb2, wb1, wb0, wb1, wb2 };
        if (interior) {
            const bool b1 = (off & 2) != 0;
            const bool b0 = (off & 1) != 0;
            const float h0 = b1 ? myq.z : myq.x;
            const float h1 = b1 ? myq.w : myq.y;
            const float h2 = b1 ? hq.x  : myq.z;
            const float h3 = b1 ? hq.y  : myq.w;
            const float h4 = b1 ? hq.z  : hq.x;
            const float h5 = b1 ? hq.w  : hq.y;
            float wv[5];
            wv[0] = b0 ? h1 : h0;
            wv[1] = b0 ? h2 : h1;
            wv[2] = b0 ? h3 : h2;
            wv[3] = b0 ? h4 : h3;
            wv[4] = b0 ? h5 : h4;
#pragma unroll
            for (int i = 0; i < 5; ++i) {
                const float rr = rv ? wv[i] : 0.0f;   // OOB row = unfold zero-pad
                const float d  = fabsf(rr - ur) * w[i];
                if ((d <= KNN_CUTOFF) && (rr >= 0.0f))
                    partAll |= (1u << (row * 5 + i));
            }
        } else {
            // edge columns (~0.25%): scalar clamped loads for this row
#pragma unroll
            for (int i = 0; i < 5; ++i) {
                const int xx = x0 + i - 2;
                const bool valid = rv && ((unsigned)xx < (unsigned)IMG_W);
                const int xxc = valid ? xx : 0;
                const float rawr = __ldg(proj_range + yyc * IMG_W + xxc);
                const float rr = valid ? rawr : 0.0f;
                const float d  = fabsf(rr - ur) * w[i];
                if ((d <= KNN_CUTOFF) && (rr >= 0.0f))
                    partAll |= (1u << (row * 5 + i));
            }
        }
    }

    // ------ combine across the point's 10 lanes in one instruction -------
    const unsigned redmask = (g < 3) ? (0x3FFu << (10 * g)) : 0xC0000000u;
    unsigned maskAll = __reduce_or_sync(redmask, partAll);
    maskAll |= (1u << 12);   // center: d forced 0, always passes, in-bounds

    if (!(pvalid && half == 0)) return;        // only gather lanes continue

    // ------ in-bounds mask arithmetically (== pass AND valid) -------------
    const int cl = (x0 < 2) ? (2 - x0) : 0;
    const int ch = (x0 > IMG_W - 3) ? (x0 - (IMG_W - 3)) : 0;
    const int rl = (y0 < 2) ? (2 - y0) : 0;
    const int rh = (y0 > IMG_H - 3) ? (y0 - (IMG_H - 3)) : 0;
    const unsigned cm     = (0x1Fu << cl) & (0x1Fu >> ch);
    const unsigned rowexp = (0x108421u << (5 * rl)) & (0x108421u >> (5 * rh));
    unsigned maskIB = (maskAll & (cm * rowexp)) | (1u << 12);

    // rare overflow (>5 cutoff passers, ~5e-4): cold exact recompute
    if (__popc(maskAll) > 5)
        maskIB = knn_exact_top5(proj_range, x0, y0, ur);

    // ------ gather channel chunk `row` for <=5 winners, store -------------
    const int gbase = y0 * IMG_W + x0;

    int kk[5];
    {
        unsigned mm = maskIB;
#pragma unroll
        for (int i = 0; i < 5; ++i) {
            kk[i] = __ffs(mm) - 1;             // -1 when exhausted
            mm &= mm - 1;
        }
    }

    float4 acc = make_float4(0.f, 0.f, 0.f, 0.f);
#pragma unroll
    for (int i = 0; i < 5; ++i) {
        const int k  = kk[i];
        const int ky = (k * 205) >> 10;        // k/5 for k in [0,24]
        const int idx = gbase + k + ky * 2043 - 4098; // = gbase+(ky-2)*W+(kx-2)
        if (k >= 0) {
            const float4 v = __ldg(probs4 + (size_t)idx * 5 + row);
            acc.x += v.x; acc.y += v.y; acc.z += v.z; acc.w += v.w;
        }
    }

    out4[(size_t)p * 5 + row] = acc;           // coalesced 80B per point
}

extern "C" void kernel_launch(void* const* d_in, const int* in_sizes, int n_in,
                              void* d_out, int out_size)
{
    const float*  proj_range = (const float*)  d_in[0];
    const float*  unproj     = (const float*)  d_in[1];
    const float4* probs4     = (const float4*) d_in[2];
    const int*    px         = (const int*)    d_in[3];
    const int*    py         = (const int*)    d_in[4];
    float4*       out4       = (float4*)       d_out;

    const int P = in_sizes[1];           // unproj_range element count
    const int blocks = (P + PTS_PER_BLK - 1) / PTS_PER_BLK;
    knn_fused<<<blocks, THREADS_FUSED>>>(proj_range, unproj, probs4,
                                         px, py, out4, P);
}

// round 16
// speedup vs baseline: 1.3755x; 1.3755x over previous
#include <cuda_runtime.h>
#include <math_constants.h>

#define IMG_H 64
#define IMG_W 2048
#define KNN_CUTOFF 1.0f

#define PTS_PER_WARP 6            // 30 active lanes, 2 idle
#define WARPS_PER_BLK 8
#define THREADS_FUSED (WARPS_PER_BLK * 32)          // 256
#define PTS_PER_BLK (WARPS_PER_BLK * PTS_PER_WARP)  // 48

// inv_g[k] = 1 - gauss(k)/sum(gauss), sigma=1, 5x5, row-major (ky,kx)
__device__ __constant__ float INV_G_C[25] = {
    0.99703098f, 0.98669378f, 0.97806177f, 0.98669378f, 0.99703098f,
    0.98669378f, 0.94036569f, 0.90167956f, 0.94036569f, 0.98669378f,
    0.97806177f, 0.90167956f, 0.83789717f, 0.90167956f, 0.97806177f,
    0.98669378f, 0.94036569f, 0.90167956f, 0.94036569f, 0.98669378f,
    0.99703098f, 0.98669378f, 0.97806177f, 0.98669378f, 0.99703098f
};

// ---------------------------------------------------------------------------
// COLD path (~65 of 131072 points): exact top-5 with reference tie-breaking.
// __noinline__ so its registers don't pollute the hot path.
// ---------------------------------------------------------------------------
__device__ __noinline__
unsigned knn_exact_top5(const float* __restrict__ proj_range,
                        int x0, int y0, float ur)
{
    unsigned key[25];
    unsigned ib = 0;
#pragma unroll
    for (int k = 0; k < 25; ++k) {
        const int yy = y0 + (k / 5) - 2;
        const int xx = x0 + (k % 5) - 2;
        const bool valid = ((unsigned)yy < (unsigned)IMG_H) &&
                           ((unsigned)xx < (unsigned)IMG_W);
        const int yyc = valid ? yy : 0;
        const int xxc = valid ? xx : 0;
        float rr = valid ? __ldg(proj_range + yyc * IMG_W + xxc) : 0.0f;
        if (rr < 0.0f) rr = CUDART_INF_F;   // matches reference
        if (k == 12)   rr = ur;             // center: d = 0
        key[k] = __float_as_uint(fabsf(rr - ur) * INV_G_C[k]);
        if (valid) ib |= (1u << k);
    }

    unsigned nm = 0;
#pragma unroll
    for (int sel = 0; sel < 5; ++sel) {
        unsigned long long best = ~0ull;
#pragma unroll
        for (int k = 0; k < 25; ++k) {
            const unsigned long long c =
                ((unsigned long long)key[k] << 32) | (unsigned)k;
            if (c < best) best = c;
        }
        const unsigned bi = (unsigned)(best & 0xFFFFFFFFu);
        nm |= (1u << bi);     // all 5 winners have d <= cutoff (>5 passers exist)
#pragma unroll
        for (int k = 0; k < 25; ++k)
            if ((unsigned)k == bi) key[k] = 0xFFFFFFFFu;
    }

    return nm & ib;           // OOB winners contribute zero probs: drop
}

// ---------------------------------------------------------------------------
// Fused kernel: 5 lanes/point, 6 points/warp (lanes 30,31 idle).
// Phase 1 (role = window row): build cutoff mask; combine via ONE REDUX.
// In-bounds contributor mask computed arithmetically from (x0,y0).
// Phase 2 (role = channel chunk): gather probs for mask winners, store.
// No smem, no __syncthreads. <=32 regs for high occupancy.
// ---------------------------------------------------------------------------
__global__ __launch_bounds__(THREADS_FUSED, 8)
void knn_fused(const float*  __restrict__ proj_range,
               const float*  __restrict__ unproj,
               const float4* __restrict__ probs4,    // [H*W][5] float4
               const int*    __restrict__ px,
               const int*    __restrict__ py,
               float4*       __restrict__ out4,      // [P][5] float4
               int P)
{
    const int tid   = threadIdx.x;
    const int wrp   = tid >> 5;
    const int lane  = tid & 31;
    const int g     = (lane * 205) >> 10;      // lane / 5 (0..6)
    const int r     = lane - g * 5;            // role: row / channel chunk
    const int p     = blockIdx.x * PTS_PER_BLK + wrp * PTS_PER_WARP + g;
    const bool active = (lane < 30) && (p < P);
    const int pc    = active ? p : 0;          // clamped: uniform loads

    // per-lane row weights (r fixed per lane -> no dynamic constant indexing)
    const int a = (r >= 2) ? (r - 2) : (2 - r);          // |r-2|
    const float wb0 = (a == 0) ? 0.83789717f : ((a == 1) ? 0.90167956f : 0.97806177f);
    const float wb1 = (a == 0) ? 0.90167956f : ((a == 1) ? 0.94036569f : 0.98669378f);
    const float wb2 = (a == 0) ? 0.97806177f : ((a == 1) ? 0.98669378f : 0.99703098f);

    const int   x0 = px[pc];
    const int   y0 = py[pc];
    const float ur = unproj[pc];

    const int  yy  = y0 + r - 2;
    const bool rv  = ((unsigned)yy < (unsigned)IMG_H);
    const int  yyc = rv ? yy : 0;

    // ---------------- phase 1: this lane's window row --------------------
    unsigned partAll = 0;
    {
        const float w[5] = { wb2, wb1, wb0, wb1, wb2 };
        if (x0 >= 2 && x0 <= IMG_W - 3) {
            const int xb   = x0 - 2;
            const int base = xb & ~3;          // aligned; W%4==0 so in-range
            const bool b1  = (xb & 2) != 0;
            const bool b0  = (xb & 1) != 0;
            const float4* rp = (const float4*)(proj_range + yyc * IMG_W + base);
            const float4 lo = __ldg(rp);
            const float4 hi = __ldg(rp + 1);
            const float h0 = b1 ? lo.z : lo.x;
            const float h1 = b1 ? lo.w : lo.y;
            const float h2 = b1 ? hi.x : lo.z;
            const float h3 = b1 ? hi.y : lo.w;
            const float h4 = b1 ? hi.z : hi.x;
            const float h5 = b1 ? hi.w : hi.y;
            float wv[5];
            wv[0] = b0 ? h1 : h0;
            wv[1] = b0 ? h2 : h1;
            wv[2] = b0 ? h3 : h2;
            wv[3] = b0 ? h4 : h3;
            wv[4] = b0 ? h5 : h4;
#pragma unroll
            for (int i = 0; i < 5; ++i) {
                const float rr = rv ? wv[i] : 0.0f;   // OOB row = unfold zero-pad
                const float d  = fabsf(rr - ur) * w[i];
                if ((d <= KNN_CUTOFF) && (rr >= 0.0f))
                    partAll |= (1u << (r * 5 + i));
            }
        } else {
            // edge columns (~0.25%): scalar clamped loads for this row
#pragma unroll
            for (int i = 0; i < 5; ++i) {
                const int xx = x0 + i - 2;
                const bool valid = rv && ((unsigned)xx < (unsigned)IMG_W);
                const int xxc = valid ? xx : 0;
                const float rawr = __ldg(proj_range + yyc * IMG_W + xxc);
                const float rr = valid ? rawr : 0.0f;
                const float d  = fabsf(rr - ur) * w[i];
                if ((d <= KNN_CUTOFF) && (rr >= 0.0f))
                    partAll |= (1u << (r * 5 + i));
            }
        }
    }

    // ---------------- combine within 5-lane group: ONE REDUX -------------
    // groups: lanes [5g, 5g+5); idle lanes 30,31 form their own group.
    const unsigned redmask = (lane < 30) ? (0x1Fu << (5 * g)) : 0xC0000000u;
    unsigned maskAll = __reduce_or_sync(redmask, partAll);
    maskAll |= (1u << 12);   // center: d forced 0, always passes, in-bounds

    if (!active) return;

    // ---------------- in-bounds contributor mask (arithmetic) ------------
    const int cl = (x0 < 2) ? (2 - x0) : 0;
    const int ch = (x0 > IMG_W - 3) ? (x0 - (IMG_W - 3)) : 0;
    const int rl = (y0 < 2) ? (2 - y0) : 0;
    const int rh = (y0 > IMG_H - 3) ? (y0 - (IMG_H - 3)) : 0;
    const unsigned cm     = (0x1Fu << cl) & (0x1Fu >> ch);
    const unsigned rowexp = (0x108421u << (5 * rl)) & (0x108421u >> (5 * rh));
    unsigned maskIB = (maskAll & (cm * rowexp)) | (1u << 12);

    // rare overflow (>5 cutoff passers, ~5e-4): cold exact recompute
    if (__popc(maskAll) > 5)
        maskIB = knn_exact_top5(proj_range, x0, y0, ur);

    // ---------------- phase 2: gather channel chunk r --------------------
    const int gbase = y0 * IMG_W + x0;

    int kk[5];
    {
        unsigned mm = maskIB;
#pragma unroll
        for (int i = 0; i < 5; ++i) {
            kk[i] = __ffs(mm) - 1;             // -1 when exhausted
            mm &= mm - 1;
        }
    }

    // accumulate on arrival (no float4 array -> fewer live registers)
    float4 acc = make_float4(0.f, 0.f, 0.f, 0.f);
#pragma unroll
    for (int i = 0; i < 5; ++i) {
        const int k  = kk[i];
        const int ky = (k * 205) >> 10;        // k/5 for k in [0,24]
        const int idx = gbase + k + ky * 2043 - 4098; // = gbase+(ky-2)*W+(kx-2)
        if (k >= 0) {
            const float4 v = __ldg(probs4 + (size_t)idx * 5 + r);
            acc.x += v.x; acc.y += v.y; acc.z += v.z; acc.w += v.w;
        }
    }

    out4[(size_t)p * 5 + r] = acc;             // coalesced 80B per point
}

extern "C" void kernel_launch(void* const* d_in, const int* in_sizes, int n_in,
                              void* d_out, int out_size)
{
    const float*  proj_range = (const float*)  d_in[0];
    const float*  unproj     = (const float*)  d_in[1];
    const float4* probs4     = (const float4*) d_in[2];
    const int*    px         = (const int*)    d_in[3];
    const int*    py         = (const int*)    d_in[4];
    float4*       out4       = (float4*)       d_out;

    const int P = in_sizes[1];           // unproj_range element count
    const int blocks = (P + PTS_PER_BLK - 1) / PTS_PER_BLK;
    knn_fused<<<blocks, THREADS_FUSED>>>(proj_range, unproj, probs4,
                                         px, py, out4, P);
}